// round 2
// baseline (speedup 1.0000x reference)
#include <cuda_runtime.h>
#include <math.h>
#include <stdint.h>

#define BB 32
#define SS 4096
#define II 512
#define HH 512
#define NCH 8
#define CHUNK (SS / NCH)      // 512 positions per block
#define TILE 16               // positions per shared tile
#define NTILES (CHUNK / TILE) // 32
#define NTHREADS 256
#define NEG_INF_F (-1e18f)

// -------- persistent device scratch (no allocations allowed) --------
__device__ float g_w2[II];             // Wk^T @ Wout
__device__ float g_qoff[BB];           // per-batch additive score offset
__device__ float g_pm[BB * NCH];       // partial max
__device__ float g_pl[BB * NCH];       // partial sumexp
__device__ float g_pkbar[BB * NCH * II]; // partial weighted key sums

// -------- cp.async helpers --------
__device__ __forceinline__ void cp_async16(void* dst_smem, const void* src_gmem) {
    unsigned d = (unsigned)__cvta_generic_to_shared(dst_smem);
    asm volatile("cp.async.cg.shared.global [%0], [%1], 16;\n" :: "r"(d), "l"(src_gmem));
}
__device__ __forceinline__ void cp_async_commit() {
    asm volatile("cp.async.commit_group;\n");
}
__device__ __forceinline__ void cp_async_wait1() {
    asm volatile("cp.async.wait_group 1;\n");
}
__device__ __forceinline__ void cp_async_wait0() {
    asm volatile("cp.async.wait_group 0;\n");
}

// ============================================================
// Kernel A: prep.  block 0: w2 = Wk^T@Wout.  block 1: qoff[b].
// ============================================================
__global__ void __launch_bounds__(512) prep_kernel(
    const float* __restrict__ query,
    const float* __restrict__ Wq, const float* __restrict__ bq,
    const float* __restrict__ Wk, const float* __restrict__ bk,
    const float* __restrict__ Wout)
{
    int tid = threadIdx.x;
    __shared__ float wout_sh[HH];
    wout_sh[tid] = Wout[tid];
    __syncthreads();

    if (blockIdx.x == 0) {
        // w2[i] = sum_h Wout[h] * Wk[h, i]
        float acc = 0.f;
        #pragma unroll 4
        for (int h = 0; h < HH; h++)
            acc += wout_sh[h] * Wk[h * II + tid];
        g_w2[tid] = acc;
    } else {
        // wq2[i] = sum_h Wout[h] * Wq[h, i]
        __shared__ float wq2_sh[II];
        __shared__ float red[512];
        float acc = 0.f;
        #pragma unroll 4
        for (int h = 0; h < HH; h++)
            acc += wout_sh[h] * Wq[h * II + tid];
        wq2_sh[tid] = acc;
        // cbias = Wout . (bq + bk)
        red[tid] = wout_sh[tid] * (bq[tid] + bk[tid]);
        __syncthreads();
        for (int off = 256; off > 0; off >>= 1) {
            if (tid < off) red[tid] += red[tid + off];
            __syncthreads();
        }
        float cbias = red[0];
        // qoff[b] = query[b,:] . wq2 + cbias   (16 threads per batch)
        int b = tid >> 4, sub = tid & 15;
        float s = 0.f;
        for (int i = sub; i < II; i += 16)
            s += query[b * II + i] * wq2_sh[i];
        #pragma unroll
        for (int off = 8; off > 0; off >>= 1)
            s += __shfl_down_sync(0xffffffffu, s, off, 16);
        if (sub == 0) g_qoff[b] = s + cbias;
    }
}

// ============================================================
// Kernel B: single streaming pass over key. Per block: one
// (batch, S-chunk). Computes scores -> attn_weight (gmem), and
// online-softmax partials (m, l, kbar) -> scratch.
// ============================================================
__global__ void __launch_bounds__(NTHREADS) main_pass(
    const float* __restrict__ key,
    const int* __restrict__ mask,
    float* __restrict__ out)
{
    const int b = blockIdx.x / NCH;
    const int c = blockIdx.x % NCH;
    const int tid = threadIdx.x;
    const int lane = tid & 31;
    const int warp = tid >> 5;
    const int s0 = c * CHUNK;
    const float* keyb = key + (size_t)b * SS * II + (size_t)s0 * II;

    extern __shared__ float smem[];
    float* buf0  = smem;                 // TILE*II floats
    float* buf1  = smem + TILE * II;     // TILE*II floats
    float* sc_sh = smem + 2 * TILE * II; // TILE scores
    float* p_sh  = sc_sh + TILE;         // TILE probs

    // w2 slice for this lane (fixed across all positions)
    float w2r[16];
    #pragma unroll
    for (int k = 0; k < 16; k++) w2r[k] = g_w2[lane + 32 * k];

    const float qoff = g_qoff[b];

    float kbar0 = 0.f, kbar1 = 0.f;  // thread owns i = tid, tid+256
    float l = 0.f;
    float m_run = -3.0e38f;

    // issue tile 0
    {
        const float* src = keyb;
        #pragma unroll
        for (int j = 0; j < 8; j++) {
            int idx = tid + j * NTHREADS; // float4 index, 2048 total
            cp_async16(buf0 + idx * 4, src + idx * 4);
        }
        cp_async_commit();
    }

    for (int t = 0; t < NTILES; t++) {
        float* cur = (t & 1) ? buf1 : buf0;
        if (t + 1 < NTILES) {
            float* nxt = (t & 1) ? buf0 : buf1;
            const float* src = keyb + (size_t)(t + 1) * TILE * II;
            #pragma unroll
            for (int j = 0; j < 8; j++) {
                int idx = tid + j * NTHREADS;
                cp_async16(nxt + idx * 4, src + idx * 4);
            }
            cp_async_commit();
            cp_async_wait1();
        } else {
            cp_async_wait0();
        }
        __syncthreads();

        // ---- scores: each warp does 2 positions ----
        for (int tt = warp; tt < TILE; tt += 8) {
            const float* kr = cur + tt * II;
            float acc = 0.f;
            #pragma unroll
            for (int k = 0; k < 16; k++)
                acc += kr[lane + 32 * k] * w2r[k];
            #pragma unroll
            for (int off = 16; off > 0; off >>= 1)
                acc += __shfl_down_sync(0xffffffffu, acc, off);
            if (lane == 0) {
                int s = s0 + t * TILE + tt;
                float sc = acc + qoff;
                if (mask[(size_t)b * SS + s] != 0) sc = NEG_INF_F;
                out[(size_t)BB * HH + (size_t)b * SS + s] = sc;
                sc_sh[tt] = sc;
            }
        }
        __syncthreads();

        // ---- online softmax update (redundant per-thread, identical) ----
        float mt = -3.0e38f;
        #pragma unroll
        for (int tt = 0; tt < TILE; tt++) mt = fmaxf(mt, sc_sh[tt]);
        float m_new = fmaxf(m_run, mt);
        float scale = __expf(m_run - m_new);

        if (tid < TILE) p_sh[tid] = __expf(sc_sh[tid] - m_new);
        __syncthreads();

        kbar0 *= scale;
        kbar1 *= scale;
        float tsum = 0.f;
        #pragma unroll
        for (int tt = 0; tt < TILE; tt++) {
            float p = p_sh[tt];
            tsum += p;
            kbar0 += p * cur[tt * II + tid];
            kbar1 += p * cur[tt * II + tid + 256];
        }
        l = l * scale + tsum;
        m_run = m_new;
        __syncthreads(); // buffer reuse fence
    }

    const int pidx = blockIdx.x;
    g_pkbar[(size_t)pidx * II + tid] = kbar0;
    g_pkbar[(size_t)pidx * II + tid + 256] = kbar1;
    if (tid == 0) { g_pm[pidx] = m_run; g_pl[pidx] = l; }
}

// ============================================================
// Kernel C: combine chunk partials, then attn = kbar @ Wk^T + bk
// ============================================================
__global__ void __launch_bounds__(512) finalize(
    const float* __restrict__ Wk, const float* __restrict__ bk,
    float* __restrict__ out)
{
    const int b = blockIdx.x;
    const int tid = threadIdx.x;
    __shared__ float kbar_sh[II];

    float M = -3.0e38f;
    #pragma unroll
    for (int c = 0; c < NCH; c++) M = fmaxf(M, g_pm[b * NCH + c]);
    float l = 0.f, kb = 0.f;
    #pragma unroll
    for (int c = 0; c < NCH; c++) {
        float w = __expf(g_pm[b * NCH + c] - M);
        l += g_pl[b * NCH + c] * w;
        kb += g_pkbar[(size_t)(b * NCH + c) * II + tid] * w;
    }
    kbar_sh[tid] = kb / l;
    __syncthreads();

    // attn[b, h] = kbar . Wk[h, :] + bk[h]
    const float4* w4 = (const float4*)(Wk + (size_t)tid * II);
    const float4* k4 = (const float4*)kbar_sh;
    float acc = bk[tid];
    #pragma unroll 8
    for (int i = 0; i < II / 4; i++) {
        float4 a = w4[i];
        float4 c4 = k4[i];
        acc += a.x * c4.x + a.y * c4.y + a.z * c4.z + a.w * c4.w;
    }
    out[b * HH + tid] = acc;
}

// ============================================================
extern "C" void kernel_launch(void* const* d_in, const int* in_sizes, int n_in,
                              void* d_out, int out_size) {
    const float* query = (const float*)d_in[0];
    const float* key   = (const float*)d_in[1];
    const int*   mask  = (const int*)d_in[2];
    const float* Wq   = (const float*)d_in[3];
    const float* bq   = (const float*)d_in[4];
    const float* Wk   = (const float*)d_in[5];
    const float* bk   = (const float*)d_in[6];
    const float* Wout = (const float*)d_in[7];
    float* out = (float*)d_out;

    const size_t smem = (2 * TILE * II + 2 * TILE) * sizeof(float); // 65664 B
    cudaFuncSetAttribute(main_pass, cudaFuncAttributeMaxDynamicSharedMemorySize, (int)smem);

    prep_kernel<<<2, 512>>>(query, Wq, bq, Wk, bk, Wout);
    main_pass<<<BB * NCH, NTHREADS, smem>>>(key, mask, out);
    finalize<<<BB, 512>>>(Wk, bk, out);
}

// round 3
// speedup vs baseline: 1.7513x; 1.7513x over previous
#include <cuda_runtime.h>
#include <math.h>
#include <stdint.h>

#define BB 32
#define SS 4096
#define II 512
#define HH 512
#define NCH 32
#define CHUNK (SS / NCH)      // 128 positions per block
#define TILE 16               // positions per shared tile
#define NTILES (CHUNK / TILE) // 8
#define NTHREADS 256
#define NEG_INF_F (-1e18f)
#define HSPLIT 8

// -------- persistent device scratch (no allocations allowed) --------
__device__ float g_part[2 * HSPLIT * II];  // [mat][hs][i] partials (0=Wk->w2, 1=Wq->wq2)
__device__ float g_w2[II];                 // Wk^T @ Wout
__device__ float g_qoff[BB];               // per-batch additive score offset
__device__ float g_pm[BB * NCH];           // partial max
__device__ float g_pl[BB * NCH];           // partial sumexp
__device__ float g_pkbar[BB * NCH * II];   // partial weighted key sums

// -------- cp.async helpers --------
__device__ __forceinline__ void cp_async16(void* dst_smem, const void* src_gmem) {
    unsigned d = (unsigned)__cvta_generic_to_shared(dst_smem);
    asm volatile("cp.async.cg.shared.global [%0], [%1], 16;\n" :: "r"(d), "l"(src_gmem));
}
__device__ __forceinline__ void cp_async_commit() {
    asm volatile("cp.async.commit_group;\n");
}
__device__ __forceinline__ void cp_async_wait1() {
    asm volatile("cp.async.wait_group 1;\n");
}
__device__ __forceinline__ void cp_async_wait0() {
    asm volatile("cp.async.wait_group 0;\n");
}

// ============================================================
// Kernel A1: partial projected-weight vectors.
// 256 blocks: mat(2) x hsplit(8) x igroup(16). 256 threads:
// il(32) x hsub(8). Coalesced 128B loads.
// ============================================================
__global__ void __launch_bounds__(256) prep_partial(
    const float* __restrict__ Wk, const float* __restrict__ Wq,
    const float* __restrict__ Wout)
{
    const int blk = blockIdx.x;
    const int mat = blk >> 7;          // 0: Wk, 1: Wq
    const int rem = blk & 127;
    const int hs  = rem >> 4;          // 0..7
    const int ig  = rem & 15;          // 0..15
    const int i0  = ig * 32;
    const int h0  = hs * 64;
    const int tid = threadIdx.x;
    const int il   = tid & 31;
    const int hsub = tid >> 5;         // 0..7

    const float* W = mat ? Wq : Wk;

    __shared__ float wout_sh[64];
    __shared__ float red[256];
    if (tid < 64) wout_sh[tid] = Wout[h0 + tid];
    __syncthreads();

    float acc = 0.f;
    #pragma unroll
    for (int k = 0; k < 8; k++) {
        int hl = hsub * 8 + k;
        acc += W[(size_t)(h0 + hl) * II + i0 + il] * wout_sh[hl];
    }
    red[tid] = acc;
    __syncthreads();
    if (tid < 128) red[tid] += red[tid + 128];
    __syncthreads();
    if (tid < 64) red[tid] += red[tid + 64];
    __syncthreads();
    if (tid < 32) {
        float v = red[tid] + red[tid + 32];
        g_part[(mat * HSPLIT + hs) * II + i0 + tid] = v;
    }
}

// ============================================================
// Kernel A2: combine partials. Blocks 0..31: qoff[b].
// Block 32: g_w2.
// ============================================================
__global__ void __launch_bounds__(512) prep_combine(
    const float* __restrict__ query,
    const float* __restrict__ bq, const float* __restrict__ bk,
    const float* __restrict__ Wout)
{
    const int tid = threadIdx.x;
    if (blockIdx.x == 32) {
        float s = 0.f;
        #pragma unroll
        for (int hs = 0; hs < HSPLIT; hs++)
            s += g_part[hs * II + tid];
        g_w2[tid] = s;
        return;
    }
    const int b = blockIdx.x;
    __shared__ float wq2_sh[II];
    __shared__ float red[512];

    float s = 0.f;
    #pragma unroll
    for (int hs = 0; hs < HSPLIT; hs++)
        s += g_part[(HSPLIT + hs) * II + tid];
    wq2_sh[tid] = s;

    // cbias = Wout . (bq + bk)
    red[tid] = Wout[tid] * (bq[tid] + bk[tid]);
    __syncthreads();
    for (int off = 256; off > 0; off >>= 1) {
        if (tid < off) red[tid] += red[tid + off];
        __syncthreads();
    }
    float cbias = red[0];
    __syncthreads();

    // qoff[b] = query[b,:] . wq2 + cbias
    red[tid] = query[(size_t)b * II + tid] * wq2_sh[tid];
    __syncthreads();
    for (int off = 256; off > 0; off >>= 1) {
        if (tid < off) red[tid] += red[tid + off];
        __syncthreads();
    }
    if (tid == 0) g_qoff[b] = red[0] + cbias;
}

// ============================================================
// Kernel B: single streaming pass over key. Per block: one
// (batch, S-chunk). Computes scores -> attn_weight (gmem), and
// online-softmax partials (m, l, kbar) -> scratch.
// ============================================================
__global__ void __launch_bounds__(NTHREADS) main_pass(
    const float* __restrict__ key,
    const int* __restrict__ mask,
    float* __restrict__ out)
{
    const int b = blockIdx.x / NCH;
    const int c = blockIdx.x % NCH;
    const int tid = threadIdx.x;
    const int lane = tid & 31;
    const int warp = tid >> 5;
    const int s0 = c * CHUNK;
    const float* keyb = key + (size_t)b * SS * II + (size_t)s0 * II;

    extern __shared__ float smem[];
    float* buf0  = smem;                 // TILE*II floats
    float* buf1  = smem + TILE * II;     // TILE*II floats
    float* sc_sh = smem + 2 * TILE * II; // TILE scores
    float* p_sh  = sc_sh + TILE;         // TILE probs

    // w2 slice for this lane (fixed across all positions)
    float w2r[16];
    #pragma unroll
    for (int k = 0; k < 16; k++) w2r[k] = g_w2[lane + 32 * k];

    const float qoff = g_qoff[b];

    float kbar0 = 0.f, kbar1 = 0.f;  // thread owns i = tid, tid+256
    float l = 0.f;
    float m_run = -3.0e38f;

    // issue tile 0
    {
        const float* src = keyb;
        #pragma unroll
        for (int j = 0; j < 8; j++) {
            int idx = tid + j * NTHREADS; // float4 index, 2048 total
            cp_async16(buf0 + idx * 4, src + idx * 4);
        }
        cp_async_commit();
    }

    for (int t = 0; t < NTILES; t++) {
        float* cur = (t & 1) ? buf1 : buf0;
        if (t + 1 < NTILES) {
            float* nxt = (t & 1) ? buf0 : buf1;
            const float* src = keyb + (size_t)(t + 1) * TILE * II;
            #pragma unroll
            for (int j = 0; j < 8; j++) {
                int idx = tid + j * NTHREADS;
                cp_async16(nxt + idx * 4, src + idx * 4);
            }
            cp_async_commit();
            cp_async_wait1();
        } else {
            cp_async_wait0();
        }
        __syncthreads();

        // ---- scores: each warp does 2 positions ----
        for (int tt = warp; tt < TILE; tt += 8) {
            const float* kr = cur + tt * II;
            float acc = 0.f;
            #pragma unroll
            for (int k = 0; k < 16; k++)
                acc += kr[lane + 32 * k] * w2r[k];
            #pragma unroll
            for (int off = 16; off > 0; off >>= 1)
                acc += __shfl_down_sync(0xffffffffu, acc, off);
            if (lane == 0) {
                int s = s0 + t * TILE + tt;
                float sc = acc + qoff;
                if (mask[(size_t)b * SS + s] != 0) sc = NEG_INF_F;
                out[(size_t)BB * HH + (size_t)b * SS + s] = sc;
                sc_sh[tt] = sc;
            }
        }
        __syncthreads();

        // ---- online softmax update (redundant per-thread, identical) ----
        float mt = -3.0e38f;
        #pragma unroll
        for (int tt = 0; tt < TILE; tt++) mt = fmaxf(mt, sc_sh[tt]);
        float m_new = fmaxf(m_run, mt);
        float scale = __expf(m_run - m_new);

        if (tid < TILE) p_sh[tid] = __expf(sc_sh[tid] - m_new);
        __syncthreads();

        kbar0 *= scale;
        kbar1 *= scale;
        float tsum = 0.f;
        #pragma unroll
        for (int tt = 0; tt < TILE; tt++) {
            float p = p_sh[tt];
            tsum += p;
            kbar0 += p * cur[tt * II + tid];
            kbar1 += p * cur[tt * II + tid + 256];
        }
        l = l * scale + tsum;
        m_run = m_new;
        __syncthreads(); // buffer reuse fence
    }

    const int pidx = blockIdx.x;
    g_pkbar[(size_t)pidx * II + tid] = kbar0;
    g_pkbar[(size_t)pidx * II + tid + 256] = kbar1;
    if (tid == 0) { g_pm[pidx] = m_run; g_pl[pidx] = l; }
}

// ============================================================
// Kernel C: combine chunk partials, then attn = kbar @ Wk^T + bk
// ============================================================
__global__ void __launch_bounds__(512) finalize(
    const float* __restrict__ Wk, const float* __restrict__ bk,
    float* __restrict__ out)
{
    const int b = blockIdx.x;
    const int tid = threadIdx.x;
    __shared__ float kbar_sh[II];

    float M = -3.0e38f;
    #pragma unroll
    for (int c = 0; c < NCH; c++) M = fmaxf(M, g_pm[b * NCH + c]);
    float l = 0.f, kb = 0.f;
    #pragma unroll
    for (int c = 0; c < NCH; c++) {
        float w = __expf(g_pm[b * NCH + c] - M);
        l += g_pl[b * NCH + c] * w;
        kb += g_pkbar[(size_t)(b * NCH + c) * II + tid] * w;
    }
    kbar_sh[tid] = kb / l;
    __syncthreads();

    // attn[b, h] = kbar . Wk[h, :] + bk[h]
    const float4* w4 = (const float4*)(Wk + (size_t)tid * II);
    const float4* k4 = (const float4*)kbar_sh;
    float acc = bk[tid];
    #pragma unroll 8
    for (int i = 0; i < II / 4; i++) {
        float4 a = w4[i];
        float4 c4 = k4[i];
        acc += a.x * c4.x + a.y * c4.y + a.z * c4.z + a.w * c4.w;
    }
    out[b * HH + tid] = acc;
}

// ============================================================
extern "C" void kernel_launch(void* const* d_in, const int* in_sizes, int n_in,
                              void* d_out, int out_size) {
    const float* query = (const float*)d_in[0];
    const float* key   = (const float*)d_in[1];
    const int*   mask  = (const int*)d_in[2];
    const float* Wq   = (const float*)d_in[3];
    const float* bq   = (const float*)d_in[4];
    const float* Wk   = (const float*)d_in[5];
    const float* bk   = (const float*)d_in[6];
    const float* Wout = (const float*)d_in[7];
    float* out = (float*)d_out;

    const size_t smem = (2 * TILE * II + 2 * TILE) * sizeof(float); // 65664 B
    cudaFuncSetAttribute(main_pass, cudaFuncAttributeMaxDynamicSharedMemorySize, (int)smem);

    prep_partial<<<256, 256>>>(Wk, Wq, Wout);
    prep_combine<<<33, 512>>>(query, bq, bk, Wout);
    main_pass<<<BB * NCH, NTHREADS, smem>>>(key, mask, out);
    finalize<<<BB, 512>>>(Wk, bk, out);
}

// round 4
// speedup vs baseline: 2.5344x; 1.4472x over previous
#include <cuda_runtime.h>
#include <math.h>
#include <stdint.h>

#define BB 32
#define SS 4096
#define II 512
#define HH 512
#define NCH 32
#define CHUNK (SS / NCH)      // 128 positions per block
#define TILE 16               // positions per shared tile
#define NTILES (CHUNK / TILE) // 8
#define NTHREADS 256
#define NEG_INF_F (-1e18f)
#define HSPLIT 8

// -------- persistent device scratch (no allocations allowed) --------
__device__ float g_part[2 * HSPLIT * II];  // [mat][hs][i] partials (0=Wk->w2, 1=Wq->wq2)
__device__ float g_w2[II];                 // Wk^T @ Wout
__device__ float g_qoff[BB];               // per-batch additive score offset
__device__ float g_pm[BB * NCH];           // partial max
__device__ float g_pl[BB * NCH];           // partial sumexp
__device__ float g_pkbar[BB * NCH * II];   // partial weighted key sums

// -------- cp.async helpers --------
__device__ __forceinline__ void cp_async16(void* dst_smem, const void* src_gmem) {
    unsigned d = (unsigned)__cvta_generic_to_shared(dst_smem);
    asm volatile("cp.async.cg.shared.global [%0], [%1], 16;\n" :: "r"(d), "l"(src_gmem));
}
__device__ __forceinline__ void cp_async_commit() {
    asm volatile("cp.async.commit_group;\n");
}
__device__ __forceinline__ void cp_async_wait1() {
    asm volatile("cp.async.wait_group 1;\n");
}
__device__ __forceinline__ void cp_async_wait0() {
    asm volatile("cp.async.wait_group 0;\n");
}

// ============================================================
// Kernel A1: partial projected-weight vectors.
// 256 blocks: mat(2) x hsplit(8) x igroup(16). 256 threads:
// il(32) x hsub(8). Coalesced 128B loads.
// ============================================================
__global__ void __launch_bounds__(256) prep_partial(
    const float* __restrict__ Wk, const float* __restrict__ Wq,
    const float* __restrict__ Wout)
{
    const int blk = blockIdx.x;
    const int mat = blk >> 7;          // 0: Wk, 1: Wq
    const int rem = blk & 127;
    const int hs  = rem >> 4;          // 0..7
    const int ig  = rem & 15;          // 0..15
    const int i0  = ig * 32;
    const int h0  = hs * 64;
    const int tid = threadIdx.x;
    const int il   = tid & 31;
    const int hsub = tid >> 5;         // 0..7

    const float* W = mat ? Wq : Wk;

    __shared__ float wout_sh[64];
    __shared__ float red[256];
    if (tid < 64) wout_sh[tid] = Wout[h0 + tid];
    __syncthreads();

    float acc = 0.f;
    #pragma unroll
    for (int k = 0; k < 8; k++) {
        int hl = hsub * 8 + k;
        acc += W[(size_t)(h0 + hl) * II + i0 + il] * wout_sh[hl];
    }
    red[tid] = acc;
    __syncthreads();
    if (tid < 128) red[tid] += red[tid + 128];
    __syncthreads();
    if (tid < 64) red[tid] += red[tid + 64];
    __syncthreads();
    if (tid < 32) {
        float v = red[tid] + red[tid + 32];
        g_part[(mat * HSPLIT + hs) * II + i0 + tid] = v;
    }
}

// ============================================================
// Kernel A2: combine partials. Blocks 0..31: qoff[b].
// Block 32: g_w2.
// ============================================================
__global__ void __launch_bounds__(512) prep_combine(
    const float* __restrict__ query,
    const float* __restrict__ bq, const float* __restrict__ bk,
    const float* __restrict__ Wout)
{
    const int tid = threadIdx.x;
    if (blockIdx.x == 32) {
        float s = 0.f;
        #pragma unroll
        for (int hs = 0; hs < HSPLIT; hs++)
            s += g_part[hs * II + tid];
        g_w2[tid] = s;
        return;
    }
    const int b = blockIdx.x;
    __shared__ float wq2_sh[II];
    __shared__ float red[512];

    float s = 0.f;
    #pragma unroll
    for (int hs = 0; hs < HSPLIT; hs++)
        s += g_part[(HSPLIT + hs) * II + tid];
    wq2_sh[tid] = s;

    // cbias = Wout . (bq + bk)
    red[tid] = Wout[tid] * (bq[tid] + bk[tid]);
    __syncthreads();
    for (int off = 256; off > 0; off >>= 1) {
        if (tid < off) red[tid] += red[tid + off];
        __syncthreads();
    }
    float cbias = red[0];
    __syncthreads();

    // qoff[b] = query[b,:] . wq2 + cbias
    red[tid] = query[(size_t)b * II + tid] * wq2_sh[tid];
    __syncthreads();
    for (int off = 256; off > 0; off >>= 1) {
        if (tid < off) red[tid] += red[tid + off];
        __syncthreads();
    }
    if (tid == 0) g_qoff[b] = red[0] + cbias;
}

// ============================================================
// Kernel B: single streaming pass over key. Per block: one
// (batch, S-chunk). Computes scores -> attn_weight (gmem), and
// online-softmax partials (m, l, kbar) -> scratch.
// ============================================================
__global__ void __launch_bounds__(NTHREADS) main_pass(
    const float* __restrict__ key,
    const int* __restrict__ mask,
    float* __restrict__ out)
{
    const int b = blockIdx.x / NCH;
    const int c = blockIdx.x % NCH;
    const int tid = threadIdx.x;
    const int lane = tid & 31;
    const int warp = tid >> 5;
    const int s0 = c * CHUNK;
    const float* keyb = key + (size_t)b * SS * II + (size_t)s0 * II;

    extern __shared__ float smem[];
    float* buf0  = smem;                 // TILE*II floats
    float* buf1  = smem + TILE * II;     // TILE*II floats
    float* sc_sh = smem + 2 * TILE * II; // TILE scores
    float* p_sh  = sc_sh + TILE;         // TILE probs

    // w2 slice for this lane (fixed across all positions)
    float w2r[16];
    #pragma unroll
    for (int k = 0; k < 16; k++) w2r[k] = g_w2[lane + 32 * k];

    const float qoff = g_qoff[b];

    float kbar0 = 0.f, kbar1 = 0.f;  // thread owns i = tid, tid+256
    float l = 0.f;
    float m_run = -3.0e38f;

    // issue tile 0
    {
        const float* src = keyb;
        #pragma unroll
        for (int j = 0; j < 8; j++) {
            int idx = tid + j * NTHREADS; // float4 index, 2048 total
            cp_async16(buf0 + idx * 4, src + idx * 4);
        }
        cp_async_commit();
    }

    for (int t = 0; t < NTILES; t++) {
        float* cur = (t & 1) ? buf1 : buf0;
        if (t + 1 < NTILES) {
            float* nxt = (t & 1) ? buf0 : buf1;
            const float* src = keyb + (size_t)(t + 1) * TILE * II;
            #pragma unroll
            for (int j = 0; j < 8; j++) {
                int idx = tid + j * NTHREADS;
                cp_async16(nxt + idx * 4, src + idx * 4);
            }
            cp_async_commit();
            cp_async_wait1();
        } else {
            cp_async_wait0();
        }
        __syncthreads();

        // ---- scores: each warp does 2 positions ----
        for (int tt = warp; tt < TILE; tt += 8) {
            const float* kr = cur + tt * II;
            float acc = 0.f;
            #pragma unroll
            for (int k = 0; k < 16; k++)
                acc += kr[lane + 32 * k] * w2r[k];
            #pragma unroll
            for (int off = 16; off > 0; off >>= 1)
                acc += __shfl_down_sync(0xffffffffu, acc, off);
            if (lane == 0) {
                int s = s0 + t * TILE + tt;
                float sc = acc + qoff;
                if (mask[(size_t)b * SS + s] != 0) sc = NEG_INF_F;
                out[(size_t)BB * HH + (size_t)b * SS + s] = sc;
                sc_sh[tt] = sc;
            }
        }
        __syncthreads();

        // ---- online softmax update (redundant per-thread, identical) ----
        float mt = -3.0e38f;
        #pragma unroll
        for (int tt = 0; tt < TILE; tt++) mt = fmaxf(mt, sc_sh[tt]);
        float m_new = fmaxf(m_run, mt);
        float scale = __expf(m_run - m_new);

        if (tid < TILE) p_sh[tid] = __expf(sc_sh[tid] - m_new);
        __syncthreads();

        kbar0 *= scale;
        kbar1 *= scale;
        float tsum = 0.f;
        #pragma unroll
        for (int tt = 0; tt < TILE; tt++) {
            float p = p_sh[tt];
            tsum += p;
            kbar0 += p * cur[tt * II + tid];
            kbar1 += p * cur[tt * II + tid + 256];
        }
        l = l * scale + tsum;
        m_run = m_new;
        __syncthreads(); // buffer reuse fence
    }

    const int pidx = blockIdx.x;
    g_pkbar[(size_t)pidx * II + tid] = kbar0;
    g_pkbar[(size_t)pidx * II + tid + 256] = kbar1;
    if (tid == 0) { g_pm[pidx] = m_run; g_pl[pidx] = l; }
}

// ============================================================
// Kernel C: combine chunk partials (redundant per h-slice block),
// then attn[b, h0:h0+64] = kbar @ Wk[h0:h0+64, :]^T + bk.
// grid = BB * 8 blocks, 256 threads.
// ============================================================
__global__ void __launch_bounds__(256) finalize(
    const float* __restrict__ Wk, const float* __restrict__ bk,
    float* __restrict__ out)
{
    const int b   = blockIdx.x >> 3;
    const int h0  = (blockIdx.x & 7) * 64;
    const int tid = threadIdx.x;
    const int lane = tid & 31;
    const int warp = tid >> 5;

    __shared__ float kbar_sh[II];
    __shared__ float pm_sh[NCH];
    __shared__ float pl_sh[NCH];

    if (tid < NCH) {
        pm_sh[tid] = g_pm[b * NCH + tid];
        pl_sh[tid] = g_pl[b * NCH + tid];
    }
    __syncthreads();

    // combine chunk partials (each thread: 2 i-values; l redundant)
    float M = -3.0e38f;
    #pragma unroll
    for (int c = 0; c < NCH; c++) M = fmaxf(M, pm_sh[c]);
    float l = 0.f, kb0 = 0.f, kb1 = 0.f;
    #pragma unroll
    for (int c = 0; c < NCH; c++) {
        float w = __expf(pm_sh[c] - M);
        l += pl_sh[c] * w;
        kb0 += g_pkbar[(size_t)(b * NCH + c) * II + tid] * w;
        kb1 += g_pkbar[(size_t)(b * NCH + c) * II + tid + 256] * w;
    }
    float invl = 1.f / l;
    kbar_sh[tid] = kb0 * invl;
    kbar_sh[tid + 256] = kb1 * invl;
    __syncthreads();

    // each warp: 8 h-dots, lane-parallel float4 over i
    const float4* k4 = (const float4*)kbar_sh;
    #pragma unroll
    for (int j = 0; j < 8; j++) {
        int h = h0 + warp * 8 + j;
        const float4* w4 = (const float4*)(Wk + (size_t)h * II);
        float acc = 0.f;
        #pragma unroll
        for (int i = 0; i < 4; i++) {
            float4 a = w4[lane + i * 32];
            float4 c4 = k4[lane + i * 32];
            acc += a.x * c4.x + a.y * c4.y + a.z * c4.z + a.w * c4.w;
        }
        #pragma unroll
        for (int off = 16; off > 0; off >>= 1)
            acc += __shfl_down_sync(0xffffffffu, acc, off);
        if (lane == 0) out[b * HH + h] = acc + bk[h];
    }
}

// ============================================================
extern "C" void kernel_launch(void* const* d_in, const int* in_sizes, int n_in,
                              void* d_out, int out_size) {
    const float* query = (const float*)d_in[0];
    const float* key   = (const float*)d_in[1];
    const int*   mask  = (const int*)d_in[2];
    const float* Wq   = (const float*)d_in[3];
    const float* bq   = (const float*)d_in[4];
    const float* Wk   = (const float*)d_in[5];
    const float* bk   = (const float*)d_in[6];
    const float* Wout = (const float*)d_in[7];
    float* out = (float*)d_out;

    const size_t smem = (2 * TILE * II + 2 * TILE) * sizeof(float); // 65664 B
    cudaFuncSetAttribute(main_pass, cudaFuncAttributeMaxDynamicSharedMemorySize, (int)smem);

    prep_partial<<<256, 256>>>(Wk, Wq, Wout);
    prep_combine<<<33, 512>>>(query, bq, bk, Wout);
    main_pass<<<BB * NCH, NTHREADS, smem>>>(key, mask, out);
    finalize<<<BB * 8, 256>>>(Wk, bk, out);
}